// round 2
// baseline (speedup 1.0000x reference)
#include <cuda_runtime.h>

// ---------------------------------------------------------------------------
// TwoLayerGCN on GB300 — round 1: fix edge_index dtype (JAX x64-off => int32).
//
// Math (per layer):
//   deg[n]  = 1 + sum_{e: dst[e]==n} ew[e]
//   dinv    = rsqrt(deg)
//   h'      = (x @ W) * dinv[row]
//   out[d]  = dinv[d] * ( sum_e h'[src[e]] * ew[e]  +  h'[d] ) + b
// Layer 1 output gets ReLU, layer 2 does not.
// ---------------------------------------------------------------------------

#define MAX_NODES 50000
#define F1 128
#define F2 64

// Scratch (allocation-free rule: __device__ globals).
__device__ float g_deg [MAX_NODES];
__device__ float g_dinv[MAX_NODES];
__device__ float g_h1  [MAX_NODES * F1];
__device__ float g_acc1[MAX_NODES * F1];
__device__ float g_x2  [MAX_NODES * F1];
__device__ float g_h2  [MAX_NODES * F2];
__device__ float g_acc2[MAX_NODES * F2];
__device__ int   g_i64;                    // 1 if edge_index is int64, 0 if int32

// Index accessor: pos in [0, 2E). Works for both dtypes.
__device__ __forceinline__ int load_idx(const void* ei, long long pos, int i64) {
    if (i64) return (int)((const long long*)ei)[pos];
    return ((const int*)ei)[pos];
}

// ---------------------------------------------------------------------------
// dtype detect: int64 data => odd int32 words are all 0 (values < 2^31).
// int32 data => odd words are src[1],src[3],... (nonzero w.h.p.).
// ---------------------------------------------------------------------------
__global__ void k_detect(const int* __restrict__ ei32) {
    __shared__ int nonzero;
    if (threadIdx.x == 0) nonzero = 0;
    __syncthreads();
    if (ei32[threadIdx.x * 2 + 1] != 0) atomicOr(&nonzero, 1);
    __syncthreads();
    if (threadIdx.x == 0) g_i64 = (nonzero == 0) ? 1 : 0;
}

// ---------------------------------------------------------------------------
// init: deg = 1 (self loop), acc1 = acc2 = 0
// ---------------------------------------------------------------------------
__global__ void k_init(int M) {
    long long total = (long long)M * F1;
    for (long long i = (long long)blockIdx.x * blockDim.x + threadIdx.x;
         i < total; i += (long long)gridDim.x * blockDim.x) {
        g_acc1[i] = 0.0f;
        if (i < (long long)M * F2) g_acc2[i] = 0.0f;
        if (i < M)                 g_deg[i]  = 1.0f;
    }
}

// ---------------------------------------------------------------------------
// weighted in-degree: deg[dst] += ew
// ---------------------------------------------------------------------------
__global__ void k_deg(const void* __restrict__ ei,
                      const float* __restrict__ ew, int E) {
    int e = blockIdx.x * blockDim.x + threadIdx.x;
    if (e >= E) return;
    int i64 = g_i64;
    int d = load_idx(ei, (long long)E + e, i64);   // dst = second row
    atomicAdd(&g_deg[d], ew[e]);
}

__global__ void k_dinv(int M) {
    int i = blockIdx.x * blockDim.x + threadIdx.x;
    if (i < M) g_dinv[i] = rsqrtf(g_deg[i]);       // deg >= 1 always
}

// ---------------------------------------------------------------------------
// C[m,n] = dinv[m] * sum_k A[m,k] * B[k,n]     (B = weight, row-major K x N)
// ---------------------------------------------------------------------------
template<int BM, int BN, int BK, int TM, int TN>
__global__ void k_gemm_scale(const float* __restrict__ A,
                             const float* __restrict__ B,
                             const float* __restrict__ dinv,
                             float* __restrict__ C,
                             int M, int K, int N) {
    __shared__ float As[BK][BM + 1];
    __shared__ float Bs[BK][BN];
    constexpr int THREADS = (BM / TM) * (BN / TN);

    const int tid  = threadIdx.x;
    const int tr   = tid / (BN / TN);
    const int tc   = tid % (BN / TN);
    const int row0 = blockIdx.x * BM;
    const int col0 = blockIdx.y * BN;

    float acc[TM][TN] = {};

    for (int k0 = 0; k0 < K; k0 += BK) {
        #pragma unroll
        for (int i = tid; i < BM * BK; i += THREADS) {
            int m = i / BK, k = i % BK;
            int gm = row0 + m;
            As[k][m] = (gm < M) ? A[(size_t)gm * K + k0 + k] : 0.0f;
        }
        #pragma unroll
        for (int i = tid; i < BK * BN; i += THREADS) {
            int k = i / BN, n = i % BN;
            Bs[k][n] = B[(size_t)(k0 + k) * N + col0 + n];
        }
        __syncthreads();

        #pragma unroll
        for (int k = 0; k < BK; k++) {
            float a[TM], b[TN];
            #pragma unroll
            for (int i = 0; i < TM; i++) a[i] = As[k][tr * TM + i];
            #pragma unroll
            for (int j = 0; j < TN; j++) b[j] = Bs[k][tc * TN + j];
            #pragma unroll
            for (int i = 0; i < TM; i++)
                #pragma unroll
                for (int j = 0; j < TN; j++)
                    acc[i][j] += a[i] * b[j];
        }
        __syncthreads();
    }

    #pragma unroll
    for (int i = 0; i < TM; i++) {
        int r = row0 + tr * TM + i;
        if (r >= M) continue;
        float s = dinv[r];
        #pragma unroll
        for (int j = 0; j < TN; j++)
            C[(size_t)r * N + col0 + tc * TN + j] = s * acc[i][j];
    }
}

// ---------------------------------------------------------------------------
// edge scatter: acc[dst] += h'[src] * ew     (F/4 threads per edge, float4)
// ---------------------------------------------------------------------------
template<int F>
__global__ void k_scatter(const void* __restrict__ ei,
                          const float* __restrict__ ew,
                          const float* __restrict__ h,
                          float* __restrict__ acc, int E) {
    constexpr int TPE = F / 4;
    long long t = (long long)blockIdx.x * blockDim.x + threadIdx.x;
    int e = (int)(t / TPE);
    int c = (int)(t % TPE);
    if (e >= E) return;

    int i64 = g_i64;
    int s = load_idx(ei, e, i64);
    int d = load_idx(ei, (long long)E + e, i64);
    float w = ew[e];

    float4 v = *reinterpret_cast<const float4*>(h + (size_t)s * F + c * 4);
    float* p = acc + (size_t)d * F + c * 4;
    atomicAdd(p + 0, v.x * w);
    atomicAdd(p + 1, v.y * w);
    atomicAdd(p + 2, v.z * w);
    atomicAdd(p + 3, v.w * w);
}

// ---------------------------------------------------------------------------
// epilogue 1: x2 = relu(dinv * (acc1 + h1) + b1)
// ---------------------------------------------------------------------------
__global__ void k_epi1(const float* __restrict__ b1, int M) {
    long long total = (long long)M * F1;
    for (long long i = (long long)blockIdx.x * blockDim.x + threadIdx.x;
         i < total; i += (long long)gridDim.x * blockDim.x) {
        int node = (int)(i / F1);
        int f    = (int)(i % F1);
        float v = g_dinv[node] * (g_acc1[i] + g_h1[i]) + b1[f];
        g_x2[i] = v > 0.0f ? v : 0.0f;
    }
}

// ---------------------------------------------------------------------------
// final: out = dinv * (acc2 + h2) + b2
// ---------------------------------------------------------------------------
__global__ void k_final(const float* __restrict__ b2,
                        float* __restrict__ out, int M) {
    long long total = (long long)M * F2;
    for (long long i = (long long)blockIdx.x * blockDim.x + threadIdx.x;
         i < total; i += (long long)gridDim.x * blockDim.x) {
        int node = (int)(i / F2);
        int f    = (int)(i % F2);
        out[i] = g_dinv[node] * (g_acc2[i] + g_h2[i]) + b2[f];
    }
}

// ---------------------------------------------------------------------------
// launch
// ---------------------------------------------------------------------------
extern "C" void kernel_launch(void* const* d_in, const int* in_sizes, int n_in,
                              void* d_out, int out_size) {
    const float* x   = (const float*)d_in[0];
    const void*  ei  = d_in[1];
    const float* ew  = (const float*)d_in[2];
    const float* W1  = (const float*)d_in[3];
    const float* b1  = (const float*)d_in[4];
    const float* W2  = (const float*)d_in[5];
    const float* b2  = (const float*)d_in[6];
    float*       out = (float*)d_out;

    const int N1 = in_sizes[4];            // 128
    const int N2 = in_sizes[6];            // 64
    const int K1 = in_sizes[3] / N1;       // 256
    const int M  = in_sizes[0] / K1;       // 50000
    const int E  = in_sizes[2];            // 1600000

    float *p_dinv, *p_h1, *p_acc1, *p_x2, *p_h2, *p_acc2;
    cudaGetSymbolAddress((void**)&p_dinv, g_dinv);
    cudaGetSymbolAddress((void**)&p_h1,   g_h1);
    cudaGetSymbolAddress((void**)&p_acc1, g_acc1);
    cudaGetSymbolAddress((void**)&p_x2,   g_x2);
    cudaGetSymbolAddress((void**)&p_h2,   g_h2);
    cudaGetSymbolAddress((void**)&p_acc2, g_acc2);

    // 0. detect edge_index dtype (int32 vs int64)
    k_detect<<<1, 256>>>((const int*)ei);

    // 1. init deg=1, acc=0
    k_init<<<1184, 256>>>(M);

    // 2. weighted degree + dinv
    k_deg <<<(E + 255) / 256, 256>>>(ei, ew, E);
    k_dinv<<<(M + 255) / 256, 256>>>(M);

    // 3. layer 1 GEMM: h1 = (x @ W1) * dinv    [M,256]x[256,128]
    {
        dim3 grid((M + 63) / 64, N1 / 64);
        k_gemm_scale<64, 64, 16, 4, 4><<<grid, 256>>>(x, W1, p_dinv, p_h1, M, K1, N1);
    }

    // 4. layer 1 scatter
    {
        long long threads = (long long)E * (F1 / 4);
        k_scatter<F1><<<(unsigned)((threads + 255) / 256), 256>>>(ei, ew, p_h1, p_acc1, E);
    }

    // 5. epilogue 1 (bias + relu)
    k_epi1<<<1184, 256>>>(b1, M);

    // 6. layer 2 GEMM: h2 = (x2 @ W2) * dinv   [M,128]x[128,64]
    {
        dim3 grid((M + 63) / 64, N2 / 64);
        k_gemm_scale<64, 64, 16, 4, 4><<<grid, 256>>>(p_x2, W2, p_dinv, p_h2, M, N1, N2);
    }

    // 7. layer 2 scatter
    {
        long long threads = (long long)E * (F2 / 4);
        k_scatter<F2><<<(unsigned)((threads + 255) / 256), 256>>>(ei, ew, p_h2, p_acc2, E);
    }

    // 8. final epilogue (bias, no relu) -> d_out
    k_final<<<1184, 256>>>(b2, out, M);
}

// round 3
// speedup vs baseline: 2.0023x; 2.0023x over previous
#include <cuda_runtime.h>

// ---------------------------------------------------------------------------
// TwoLayerGCN on GB300 — round 3: CSR counting-sort + atomic-free aggregation.
//
//   deg[n]  = 1 + sum_{e: dst[e]==n} ew[e]
//   dinv    = rsqrt(deg)
//   h'      = (x @ W) * dinv[row]
//   out[d]  = dinv[d] * ( sum_e h'[src[e]] * ew[e]  +  h'[d] ) + b
// ---------------------------------------------------------------------------

#define MAX_NODES 50000
#define MAX_EDGES 1600000
#define F1 128
#define F2 64

// Scratch (__device__ globals; no allocation allowed).
__device__ int   g_count [MAX_NODES];
__device__ int   g_row   [MAX_NODES + 1];
__device__ int   g_cursor[MAX_NODES];
__device__ int   g_esrc  [MAX_EDGES];
__device__ float g_ewsrt [MAX_EDGES];
__device__ float g_dinv  [MAX_NODES];
__device__ float g_h1    [MAX_NODES * F1];
__device__ float g_x2    [MAX_NODES * F1];
__device__ float g_h2    [MAX_NODES * F2];
__device__ int   g_i64;

__device__ __forceinline__ int load_idx(const void* ei, long long pos, int i64) {
    if (i64) return (int)((const long long*)ei)[pos];
    return ((const int*)ei)[pos];
}

// dtype detect: int64 values < 2^31 => odd 32-bit words all zero.
__global__ void k_detect(const int* __restrict__ ei32) {
    __shared__ int nonzero;
    if (threadIdx.x == 0) nonzero = 0;
    __syncthreads();
    if (ei32[threadIdx.x * 2 + 1] != 0) atomicOr(&nonzero, 1);
    __syncthreads();
    if (threadIdx.x == 0) g_i64 = (nonzero == 0) ? 1 : 0;
}

__global__ void k_zero(int M) {
    int i = blockIdx.x * blockDim.x + threadIdx.x;
    if (i < M) g_count[i] = 0;
}

// histogram over dst
__global__ void k_hist(const void* __restrict__ ei, int E) {
    int e = blockIdx.x * blockDim.x + threadIdx.x;
    if (e >= E) return;
    int d = load_idx(ei, (long long)E + e, g_i64);
    atomicAdd(&g_count[d], 1);
}

// single-block exclusive scan of g_count -> g_row, g_cursor
__global__ void k_scan(int M) {
    __shared__ int sdata[1024];
    __shared__ int carry_s;
    const int tid = threadIdx.x;
    if (tid == 0) carry_s = 0;
    __syncthreads();

    for (int base = 0; base < M; base += 1024) {
        int i = base + tid;
        int v = (i < M) ? g_count[i] : 0;
        sdata[tid] = v;
        __syncthreads();
        // Hillis-Steele inclusive scan
        for (int off = 1; off < 1024; off <<= 1) {
            int t = (tid >= off) ? sdata[tid - off] : 0;
            __syncthreads();
            sdata[tid] += t;
            __syncthreads();
        }
        int carry = carry_s;
        int excl = carry + sdata[tid] - v;
        if (i < M) { g_row[i] = excl; g_cursor[i] = excl; }
        __syncthreads();
        if (tid == 1023) carry_s = carry + sdata[1023];
        __syncthreads();
    }
    if (tid == 0) g_row[M] = carry_s;
}

// fill sorted-by-dst edge arrays
__global__ void k_fill(const void* __restrict__ ei,
                       const float* __restrict__ ew, int E) {
    int e = blockIdx.x * blockDim.x + threadIdx.x;
    if (e >= E) return;
    int i64 = g_i64;
    int s = load_idx(ei, e, i64);
    int d = load_idx(ei, (long long)E + e, i64);
    int pos = atomicAdd(&g_cursor[d], 1);
    g_esrc[pos]  = s;
    g_ewsrt[pos] = ew[e];
}

// dinv[n] = rsqrt(1 + sum of incoming weights)   (warp per node)
__global__ void k_dinv_csr(int M) {
    int warp = (blockIdx.x * blockDim.x + threadIdx.x) >> 5;
    int lane = threadIdx.x & 31;
    if (warp >= M) return;
    int r0 = g_row[warp], r1 = g_row[warp + 1];
    float sum = 0.0f;
    for (int i = r0 + lane; i < r1; i += 32) sum += g_ewsrt[i];
    #pragma unroll
    for (int off = 16; off > 0; off >>= 1)
        sum += __shfl_xor_sync(0xffffffffu, sum, off);
    if (lane == 0) g_dinv[warp] = rsqrtf(1.0f + sum);
}

// ---------------------------------------------------------------------------
// C[m,n] = dinv[m] * sum_k A[m,k] * B[k,n]
// ---------------------------------------------------------------------------
template<int BM, int BN, int BK, int TM, int TN>
__global__ void k_gemm_scale(const float* __restrict__ A,
                             const float* __restrict__ B,
                             const float* __restrict__ dinv,
                             float* __restrict__ C,
                             int M, int K, int N) {
    __shared__ float As[BK][BM + 1];
    __shared__ float Bs[BK][BN];
    constexpr int THREADS = (BM / TM) * (BN / TN);

    const int tid  = threadIdx.x;
    const int tr   = tid / (BN / TN);
    const int tc   = tid % (BN / TN);
    const int row0 = blockIdx.x * BM;
    const int col0 = blockIdx.y * BN;

    float acc[TM][TN] = {};

    for (int k0 = 0; k0 < K; k0 += BK) {
        #pragma unroll
        for (int i = tid; i < BM * BK; i += THREADS) {
            int m = i / BK, k = i % BK;
            int gm = row0 + m;
            As[k][m] = (gm < M) ? A[(size_t)gm * K + k0 + k] : 0.0f;
        }
        #pragma unroll
        for (int i = tid; i < BK * BN; i += THREADS) {
            int k = i / BN, n = i % BN;
            Bs[k][n] = B[(size_t)(k0 + k) * N + col0 + n];
        }
        __syncthreads();

        #pragma unroll
        for (int k = 0; k < BK; k++) {
            float a[TM], b[TN];
            #pragma unroll
            for (int i = 0; i < TM; i++) a[i] = As[k][tr * TM + i];
            #pragma unroll
            for (int j = 0; j < TN; j++) b[j] = Bs[k][tc * TN + j];
            #pragma unroll
            for (int i = 0; i < TM; i++)
                #pragma unroll
                for (int j = 0; j < TN; j++)
                    acc[i][j] += a[i] * b[j];
        }
        __syncthreads();
    }

    #pragma unroll
    for (int i = 0; i < TM; i++) {
        int r = row0 + tr * TM + i;
        if (r >= M) continue;
        float s = dinv[r];
        #pragma unroll
        for (int j = 0; j < TN; j++)
            C[(size_t)r * N + col0 + tc * TN + j] = s * acc[i][j];
    }
}

// ---------------------------------------------------------------------------
// aggregation: out[d] = act( dinv[d]*(sum_edges h[src]*w + h[d]) + bias )
// warp per node; lane owns VEC consecutive columns; edges broadcast via shfl.
// ---------------------------------------------------------------------------
template<int F, int VEC, bool RELU>
__global__ void k_agg(const float* __restrict__ h,
                      const float* __restrict__ bias,
                      float* __restrict__ out, int M) {
    static_assert(F == 32 * VEC, "lane layout");
    int warp = (blockIdx.x * blockDim.x + threadIdx.x) >> 5;
    int lane = threadIdx.x & 31;
    if (warp >= M) return;

    const int r0 = g_row[warp], r1 = g_row[warp + 1];
    float acc[VEC] = {};

    for (int base = r0; base < r1; base += 32) {
        int n = r1 - base; if (n > 32) n = 32;
        int   s = 0; float w = 0.0f;
        if (lane < n) { s = g_esrc[base + lane]; w = g_ewsrt[base + lane]; }
        for (int j = 0; j < n; j++) {
            int   sj = __shfl_sync(0xffffffffu, s, j);
            float wj = __shfl_sync(0xffffffffu, w, j);
            const float* p = h + (size_t)sj * F + lane * VEC;
            if (VEC == 4) {
                float4 v = *reinterpret_cast<const float4*>(p);
                acc[0] += v.x * wj; acc[1] += v.y * wj;
                acc[2] += v.z * wj; acc[3] += v.w * wj;
            } else {
                float2 v = *reinterpret_cast<const float2*>(p);
                acc[0] += v.x * wj; acc[1] += v.y * wj;
            }
        }
    }

    // self-loop term (w=1): + h[d]
    const float* ps = h + (size_t)warp * F + lane * VEC;
    float di = g_dinv[warp];
    float r[VEC];
    #pragma unroll
    for (int k = 0; k < VEC; k++) {
        float v = ps[k];
        float o = di * (acc[k] + v) + bias[lane * VEC + k];
        r[k] = (RELU && o < 0.0f) ? 0.0f : o;
    }
    float* po = out + (size_t)warp * F + lane * VEC;
    if (VEC == 4) *reinterpret_cast<float4*>(po) = make_float4(r[0], r[1], r[2], r[3]);
    else          *reinterpret_cast<float2*>(po) = make_float2(r[0], r[1]);
}

// ---------------------------------------------------------------------------
extern "C" void kernel_launch(void* const* d_in, const int* in_sizes, int n_in,
                              void* d_out, int out_size) {
    const float* x   = (const float*)d_in[0];
    const void*  ei  = d_in[1];
    const float* ew  = (const float*)d_in[2];
    const float* W1  = (const float*)d_in[3];
    const float* b1  = (const float*)d_in[4];
    const float* W2  = (const float*)d_in[5];
    const float* b2  = (const float*)d_in[6];
    float*       out = (float*)d_out;

    const int N1 = in_sizes[4];            // 128
    const int N2 = in_sizes[6];            // 64
    const int K1 = in_sizes[3] / N1;       // 256
    const int M  = in_sizes[0] / K1;       // 50000
    const int E  = in_sizes[2];            // 1600000

    float *p_dinv, *p_h1, *p_x2, *p_h2;
    cudaGetSymbolAddress((void**)&p_dinv, g_dinv);
    cudaGetSymbolAddress((void**)&p_h1,   g_h1);
    cudaGetSymbolAddress((void**)&p_x2,   g_x2);
    cudaGetSymbolAddress((void**)&p_h2,   g_h2);

    // --- CSR build ---
    k_detect<<<1, 256>>>((const int*)ei);
    k_zero  <<<(M + 255) / 256, 256>>>(M);
    k_hist  <<<(E + 255) / 256, 256>>>(ei, E);
    k_scan  <<<1, 1024>>>(M);
    k_fill  <<<(E + 255) / 256, 256>>>(ei, ew, E);
    k_dinv_csr<<<(M * 32 + 255) / 256, 256>>>(M);

    // --- layer 1 ---
    {
        dim3 grid((M + 63) / 64, N1 / 64);
        k_gemm_scale<64, 64, 16, 4, 4><<<grid, 256>>>(x, W1, p_dinv, p_h1, M, K1, N1);
    }
    k_agg<F1, 4, true><<<(M * 32 + 255) / 256, 256>>>(p_h1, b1, p_x2, M);

    // --- layer 2 ---
    {
        dim3 grid((M + 63) / 64, N2 / 64);
        k_gemm_scale<64, 64, 16, 4, 4><<<grid, 256>>>(p_x2, W2, p_dinv, p_h2, M, N1, N2);
    }
    k_agg<F2, 2, false><<<(M * 32 + 255) / 256, 256>>>(p_h2, b2, out, M);
}

// round 4
// speedup vs baseline: 2.7007x; 1.3488x over previous
#include <cuda_runtime.h>

// ---------------------------------------------------------------------------
// TwoLayerGCN on GB300 — round 4: fast scan, retiled GEMM, unrolled gather.
//
//   deg[n]  = 1 + sum_{e: dst[e]==n} ew[e]
//   dinv    = rsqrt(deg)
//   h'      = (x @ W) * dinv[row]
//   out[d]  = dinv[d] * ( sum_e h'[src[e]] * ew[e]  +  h'[d] ) + b
// ---------------------------------------------------------------------------

#define MAX_NODES 50000
#define MAX_EDGES 1600000
#define F1 128
#define F2 64

__device__ int   g_count [MAX_NODES];
__device__ int   g_row   [MAX_NODES + 1];
__device__ int   g_cursor[MAX_NODES];
__device__ int   g_esrc  [MAX_EDGES];
__device__ float g_ewsrt [MAX_EDGES];
__device__ float g_dinv  [MAX_NODES];
__device__ float g_h1    [MAX_NODES * F1];
__device__ float g_x2    [MAX_NODES * F1];
__device__ float g_h2    [MAX_NODES * F2];
__device__ int   g_i64;

__device__ __forceinline__ int load_idx(const void* ei, long long pos, int i64) {
    if (i64) return (int)((const long long*)ei)[pos];
    return ((const int*)ei)[pos];
}

// dtype detect: int64 values < 2^31 => odd 32-bit words all zero.
__global__ void k_detect(const int* __restrict__ ei32) {
    __shared__ int nonzero;
    if (threadIdx.x == 0) nonzero = 0;
    __syncthreads();
    if (ei32[threadIdx.x * 2 + 1] != 0) atomicOr(&nonzero, 1);
    __syncthreads();
    if (threadIdx.x == 0) g_i64 = (nonzero == 0) ? 1 : 0;
}

__global__ void k_zero(int M) {
    int i = blockIdx.x * blockDim.x + threadIdx.x;
    if (i < M) g_count[i] = 0;
}

__global__ void k_hist(const void* __restrict__ ei, int E) {
    int e = blockIdx.x * blockDim.x + threadIdx.x;
    if (e >= E) return;
    int d = load_idx(ei, (long long)E + e, g_i64);
    atomicAdd(&g_count[d], 1);
}

// ---------------------------------------------------------------------------
// single-block blocked scan: thread t owns chunk [t*PER, (t+1)*PER).
// serial chunk sum -> warp shfl scan -> 32-warp scan -> serial prefix write.
// 2 barriers total (vs ~1000 in the Hillis-Steele version).
// ---------------------------------------------------------------------------
__global__ void k_scan(int M) {
    const int tid  = threadIdx.x;
    const int lane = tid & 31;
    const int wid  = tid >> 5;
    const int PER  = (M + 1023) / 1024;
    const int start = tid * PER;
    const int end   = min(start + PER, M);

    int sum = 0;
    for (int i = start; i < end; i++) sum += g_count[i];

    // inclusive warp scan of per-thread sums
    int v = sum;
    #pragma unroll
    for (int off = 1; off < 32; off <<= 1) {
        int t = __shfl_up_sync(0xffffffffu, v, off);
        if (lane >= off) v += t;
    }
    __shared__ int wsum[32];
    if (lane == 31) wsum[wid] = v;
    __syncthreads();
    if (wid == 0) {
        int w = wsum[lane];
        #pragma unroll
        for (int off = 1; off < 32; off <<= 1) {
            int t = __shfl_up_sync(0xffffffffu, w, off);
            if (lane >= off) w += t;
        }
        wsum[lane] = w;                      // inclusive warp prefix
    }
    __syncthreads();

    int thread_excl = (v - sum) + (wid > 0 ? wsum[wid - 1] : 0);
    int run = thread_excl;
    for (int i = start; i < end; i++) {
        int c = g_count[i];
        g_row[i] = run; g_cursor[i] = run;
        run += c;
    }
    if (tid == 0) g_row[M] = wsum[31];       // total
}

__global__ void k_fill(const void* __restrict__ ei,
                       const float* __restrict__ ew, int E) {
    int e = blockIdx.x * blockDim.x + threadIdx.x;
    if (e >= E) return;
    int i64 = g_i64;
    int s = load_idx(ei, e, i64);
    int d = load_idx(ei, (long long)E + e, i64);
    int pos = atomicAdd(&g_cursor[d], 1);
    g_esrc[pos]  = s;
    g_ewsrt[pos] = ew[e];
}

// dinv[n] = rsqrt(1 + sum of incoming weights)
__global__ void k_dinv_csr(int M) {
    int warp = (blockIdx.x * blockDim.x + threadIdx.x) >> 5;
    int lane = threadIdx.x & 31;
    if (warp >= M) return;
    int r0 = g_row[warp], r1 = g_row[warp + 1];
    float sum = 0.0f;
    for (int i = r0 + lane; i < r1; i += 32) sum += g_ewsrt[i];
    #pragma unroll
    for (int off = 16; off > 0; off >>= 1)
        sum += __shfl_xor_sync(0xffffffffu, sum, off);
    if (lane == 0) g_dinv[warp] = rsqrtf(1.0f + sum);
}

// ---------------------------------------------------------------------------
// C[m,n] = dinv[m] * sum_k A[m,k] * B[k,n]
// BM=128, BN=64, BK=16, TM=8, TN=4, 256 threads. float4 everywhere.
// ---------------------------------------------------------------------------
__global__ void k_gemm_scale(const float* __restrict__ A,
                             const float* __restrict__ B,
                             const float* __restrict__ dinv,
                             float* __restrict__ C,
                             int M, int K, int N) {
    constexpr int BM = 128, BN = 64, BK = 16, TM = 8, TN = 4;
    __shared__ float As[BK][BM + 4];
    __shared__ float Bs[BK][BN];

    const int tid  = threadIdx.x;                 // 256 threads
    const int tr   = tid / (BN / TN);             // 0..15
    const int tc   = tid % (BN / TN);             // 0..15
    const int row0 = blockIdx.x * BM;
    const int col0 = blockIdx.y * BN;

    float acc[TM][TN] = {};

    for (int k0 = 0; k0 < K; k0 += BK) {
        // A tile: 128 rows x 16 cols = 512 float4s, 2 per thread (transposed store)
        #pragma unroll
        for (int i = tid; i < BM * (BK / 4); i += 256) {
            int m  = i / (BK / 4);
            int c4 = i % (BK / 4);
            int gm = row0 + m;
            float4 v = make_float4(0.f, 0.f, 0.f, 0.f);
            if (gm < M)
                v = *reinterpret_cast<const float4*>(A + (size_t)gm * K + k0 + c4 * 4);
            As[c4 * 4 + 0][m] = v.x;
            As[c4 * 4 + 1][m] = v.y;
            As[c4 * 4 + 2][m] = v.z;
            As[c4 * 4 + 3][m] = v.w;
        }
        // B tile: 16 rows x 64 cols = 256 float4s, 1 per thread
        {
            int i  = tid;
            int k  = i / (BN / 4);
            int c4 = i % (BN / 4);
            float4 v = *reinterpret_cast<const float4*>(B + (size_t)(k0 + k) * N + col0 + c4 * 4);
            *reinterpret_cast<float4*>(&Bs[k][c4 * 4]) = v;
        }
        __syncthreads();

        #pragma unroll
        for (int k = 0; k < BK; k++) {
            float a[TM], b[TN];
            #pragma unroll
            for (int i = 0; i < TM; i++) a[i] = As[k][tr * TM + i];
            #pragma unroll
            for (int j = 0; j < TN; j++) b[j] = Bs[k][tc * TN + j];
            #pragma unroll
            for (int i = 0; i < TM; i++)
                #pragma unroll
                for (int j = 0; j < TN; j++)
                    acc[i][j] += a[i] * b[j];
        }
        __syncthreads();
    }

    #pragma unroll
    for (int i = 0; i < TM; i++) {
        int r = row0 + tr * TM + i;
        if (r >= M) continue;
        float s = dinv[r];
        float4 o = make_float4(s * acc[i][0], s * acc[i][1], s * acc[i][2], s * acc[i][3]);
        *reinterpret_cast<float4*>(C + (size_t)r * N + col0 + tc * TN) = o;
    }
}

// ---------------------------------------------------------------------------
// aggregation: out[d] = act( dinv[d]*(sum_edges h[src]*w + h[d]) + bias )
// warp per node; lane owns VEC columns; full 32-edge blocks unrolled for MLP.
// ---------------------------------------------------------------------------
template<int F, int VEC, bool RELU>
__global__ void k_agg(const float* __restrict__ h,
                      const float* __restrict__ bias,
                      float* __restrict__ out, int M) {
    static_assert(F == 32 * VEC, "lane layout");
    int warp = (blockIdx.x * blockDim.x + threadIdx.x) >> 5;
    int lane = threadIdx.x & 31;
    if (warp >= M) return;

    const int r0 = g_row[warp], r1 = g_row[warp + 1];
    const int nfull = r0 + (((r1 - r0) >> 5) << 5);
    float acc[VEC] = {};

    // full 32-edge blocks: fixed trip count, unrolled -> 4+ gathers in flight
    for (int base = r0; base < nfull; base += 32) {
        int   s = g_esrc [base + lane];
        float w = g_ewsrt[base + lane];
        #pragma unroll 4
        for (int j = 0; j < 32; j++) {
            int   sj = __shfl_sync(0xffffffffu, s, j);
            float wj = __shfl_sync(0xffffffffu, w, j);
            const float* p = h + (size_t)sj * F + lane * VEC;
            if (VEC == 4) {
                float4 v = *reinterpret_cast<const float4*>(p);
                acc[0] += v.x * wj; acc[1] += v.y * wj;
                acc[2] += v.z * wj; acc[3] += v.w * wj;
            } else {
                float2 v = *reinterpret_cast<const float2*>(p);
                acc[0] += v.x * wj; acc[1] += v.y * wj;
            }
        }
    }
    // remainder
    {
        int n = r1 - nfull;
        int   s = 0; float w = 0.0f;
        if (lane < n) { s = g_esrc[nfull + lane]; w = g_ewsrt[nfull + lane]; }
        for (int j = 0; j < n; j++) {
            int   sj = __shfl_sync(0xffffffffu, s, j);
            float wj = __shfl_sync(0xffffffffu, w, j);
            const float* p = h + (size_t)sj * F + lane * VEC;
            if (VEC == 4) {
                float4 v = *reinterpret_cast<const float4*>(p);
                acc[0] += v.x * wj; acc[1] += v.y * wj;
                acc[2] += v.z * wj; acc[3] += v.w * wj;
            } else {
                float2 v = *reinterpret_cast<const float2*>(p);
                acc[0] += v.x * wj; acc[1] += v.y * wj;
            }
        }
    }

    // self-loop (w=1), dinv scale, bias, activation
    const float* ps = h + (size_t)warp * F + lane * VEC;
    float di = g_dinv[warp];
    float r[VEC];
    #pragma unroll
    for (int k = 0; k < VEC; k++) {
        float o = di * (acc[k] + ps[k]) + bias[lane * VEC + k];
        r[k] = (RELU && o < 0.0f) ? 0.0f : o;
    }
    float* po = out + (size_t)warp * F + lane * VEC;
    if (VEC == 4) *reinterpret_cast<float4*>(po) = make_float4(r[0], r[1], r[2], r[3]);
    else          *reinterpret_cast<float2*>(po) = make_float2(r[0], r[1]);
}

// ---------------------------------------------------------------------------
extern "C" void kernel_launch(void* const* d_in, const int* in_sizes, int n_in,
                              void* d_out, int out_size) {
    const float* x   = (const float*)d_in[0];
    const void*  ei  = d_in[1];
    const float* ew  = (const float*)d_in[2];
    const float* W1  = (const float*)d_in[3];
    const float* b1  = (const float*)d_in[4];
    const float* W2  = (const float*)d_in[5];
    const float* b2  = (const float*)d_in[6];
    float*       out = (float*)d_out;

    const int N1 = in_sizes[4];            // 128
    const int N2 = in_sizes[6];            // 64
    const int K1 = in_sizes[3] / N1;       // 256
    const int M  = in_sizes[0] / K1;       // 50000
    const int E  = in_sizes[2];            // 1600000

    float *p_dinv, *p_h1, *p_x2, *p_h2;
    cudaGetSymbolAddress((void**)&p_dinv, g_dinv);
    cudaGetSymbolAddress((void**)&p_h1,   g_h1);
    cudaGetSymbolAddress((void**)&p_x2,   g_x2);
    cudaGetSymbolAddress((void**)&p_h2,   g_h2);

    // --- CSR build ---
    k_detect<<<1, 256>>>((const int*)ei);
    k_zero  <<<(M + 255) / 256, 256>>>(M);
    k_hist  <<<(E + 255) / 256, 256>>>(ei, E);
    k_scan  <<<1, 1024>>>(M);
    k_fill  <<<(E + 255) / 256, 256>>>(ei, ew, E);
    k_dinv_csr<<<(M * 32 + 255) / 256, 256>>>(M);

    // --- layer 1 ---
    {
        dim3 grid((M + 127) / 128, N1 / 64);
        k_gemm_scale<<<grid, 256>>>(x, W1, p_dinv, p_h1, M, K1, N1);
    }
    k_agg<F1, 4, true><<<(M * 32 + 255) / 256, 256>>>(p_h1, b1, p_x2, M);

    // --- layer 2 ---
    {
        dim3 grid((M + 127) / 128, N2 / 64);
        k_gemm_scale<<<grid, 256>>>(p_x2, W2, p_dinv, p_h2, M, N1, N2);
    }
    k_agg<F2, 2, false><<<(M * 32 + 255) / 256, 256>>>(p_h2, b2, out, M);
}

// round 5
// speedup vs baseline: 3.3820x; 1.2523x over previous
#include <cuda_runtime.h>

// ---------------------------------------------------------------------------
// TwoLayerGCN on GB300 — round 5: chip-wide decoupled scan, fused CSR build,
// packed edge records.
//
//   deg[n]  = 1 + sum_{e: dst[e]==n} ew[e]
//   dinv    = rsqrt(deg)
//   h'      = (x @ W) * dinv[row]
//   out[d]  = dinv[d] * ( sum_e h'[src[e]] * ew[e]  +  h'[d] ) + b
// ---------------------------------------------------------------------------

#define MAX_NODES 50000
#define MAX_EDGES 1600000
#define F1 128
#define F2 64
#define SCAN_CHUNK 256
#define NUM_CHUNKS ((MAX_NODES + SCAN_CHUNK - 1) / SCAN_CHUNK)   // 196

__device__ int   g_count [MAX_NODES];
__device__ float g_deg   [MAX_NODES];
__device__ int   g_row   [MAX_NODES + 1];
__device__ int   g_cursor[MAX_NODES];
__device__ int   g_bsum  [NUM_CHUNKS];
__device__ int   g_bpre  [NUM_CHUNKS];
__device__ int2  g_edge  [MAX_EDGES];      // (src, __float_as_int(w)) sorted by dst
__device__ float g_dinv  [MAX_NODES];
__device__ float g_h1    [MAX_NODES * F1];
__device__ float g_x2    [MAX_NODES * F1];
__device__ float g_h2    [MAX_NODES * F2];
__device__ int   g_i64;

__device__ __forceinline__ int load_idx(const void* ei, long long pos, int i64) {
    if (i64) return (int)((const long long*)ei)[pos];
    return ((const int*)ei)[pos];
}

// dtype detect: int64 values < 2^31 => odd 32-bit words all zero.
__global__ void k_detect(const int* __restrict__ ei32) {
    __shared__ int nonzero;
    if (threadIdx.x == 0) nonzero = 0;
    __syncthreads();
    if (ei32[threadIdx.x * 2 + 1] != 0) atomicOr(&nonzero, 1);
    __syncthreads();
    if (threadIdx.x == 0) g_i64 = (nonzero == 0) ? 1 : 0;
}

__global__ void k_zero(int M) {
    int i = blockIdx.x * blockDim.x + threadIdx.x;
    if (i < M) { g_count[i] = 0; g_deg[i] = 1.0f; }   // deg starts at 1 (self loop)
}

// fused histogram + weighted degree
__global__ void k_histdeg(const void* __restrict__ ei,
                          const float* __restrict__ ew, int E) {
    int e = blockIdx.x * blockDim.x + threadIdx.x;
    if (e >= E) return;
    int d = load_idx(ei, (long long)E + e, g_i64);
    atomicAdd(&g_count[d], 1);
    atomicAdd(&g_deg[d], ew[e]);
}

// --- decoupled scan, pass 1: per-chunk sums (196 blocks x 256 threads) ---
__global__ void k_partial(int M) {
    __shared__ int wsum[8];
    int i = blockIdx.x * SCAN_CHUNK + threadIdx.x;
    int lane = threadIdx.x & 31, wid = threadIdx.x >> 5;
    int v = (i < M) ? g_count[i] : 0;
    #pragma unroll
    for (int off = 16; off > 0; off >>= 1)
        v += __shfl_xor_sync(0xffffffffu, v, off);
    if (lane == 0) wsum[wid] = v;
    __syncthreads();
    if (threadIdx.x == 0) {
        int s = 0;
        #pragma unroll
        for (int w = 0; w < 8; w++) s += wsum[w];
        g_bsum[blockIdx.x] = s;
    }
}

// --- pass 2: exclusive scan of chunk sums (1 block, NB <= 256) ---
__global__ void k_scanb(int NB) {
    __shared__ int wpre[8];
    int tid = threadIdx.x, lane = tid & 31, wid = tid >> 5;
    int v = (tid < NB) ? g_bsum[tid] : 0;
    int inc = v;
    #pragma unroll
    for (int off = 1; off < 32; off <<= 1) {
        int t = __shfl_up_sync(0xffffffffu, inc, off);
        if (lane >= off) inc += t;
    }
    if (lane == 31) wpre[wid] = inc;
    __syncthreads();
    if (wid == 0) {
        int w = (lane < 8) ? wpre[lane] : 0;
        #pragma unroll
        for (int off = 1; off < 8; off <<= 1) {
            int t = __shfl_up_sync(0xffffffffu, w, off);
            if (lane >= off) w += t;
        }
        if (lane < 8) wpre[lane] = w;
    }
    __syncthreads();
    int excl = inc - v + (wid > 0 ? wpre[wid - 1] : 0);
    if (tid < NB) g_bpre[tid] = excl;
}

// --- pass 3: write row offsets + cursor + dinv (fused) ---
__global__ void k_write(int M) {
    __shared__ int wpre[8];
    int i = blockIdx.x * SCAN_CHUNK + threadIdx.x;
    int lane = threadIdx.x & 31, wid = threadIdx.x >> 5;
    int c = (i < M) ? g_count[i] : 0;
    int inc = c;
    #pragma unroll
    for (int off = 1; off < 32; off <<= 1) {
        int t = __shfl_up_sync(0xffffffffu, inc, off);
        if (lane >= off) inc += t;
    }
    if (lane == 31) wpre[wid] = inc;
    __syncthreads();
    if (wid == 0) {
        int w = (lane < 8) ? wpre[lane] : 0;
        #pragma unroll
        for (int off = 1; off < 8; off <<= 1) {
            int t = __shfl_up_sync(0xffffffffu, w, off);
            if (lane >= off) w += t;
        }
        if (lane < 8) wpre[lane] = w;
    }
    __syncthreads();
    int excl = inc - c + (wid > 0 ? wpre[wid - 1] : 0) + g_bpre[blockIdx.x];
    if (i < M) {
        g_row[i]    = excl;
        g_cursor[i] = excl;
        g_dinv[i]   = rsqrtf(g_deg[i]);
        if (i == M - 1) g_row[M] = excl + c;
    }
}

// fill sorted-by-dst packed edge records
__global__ void k_fill(const void* __restrict__ ei,
                       const float* __restrict__ ew, int E) {
    int e = blockIdx.x * blockDim.x + threadIdx.x;
    if (e >= E) return;
    int i64 = g_i64;
    int s = load_idx(ei, e, i64);
    int d = load_idx(ei, (long long)E + e, i64);
    int pos = atomicAdd(&g_cursor[d], 1);
    g_edge[pos] = make_int2(s, __float_as_int(ew[e]));
}

// ---------------------------------------------------------------------------
// C[m,n] = dinv[m] * sum_k A[m,k] * B[k,n]
// BM=128, BN=64, BK=16, TM=8, TN=4, 256 threads, float4 everywhere.
// ---------------------------------------------------------------------------
__global__ void k_gemm_scale(const float* __restrict__ A,
                             const float* __restrict__ B,
                             const float* __restrict__ dinv,
                             float* __restrict__ C,
                             int M, int K, int N) {
    constexpr int BM = 128, BN = 64, BK = 16, TM = 8, TN = 4;
    __shared__ float As[BK][BM + 4];
    __shared__ float Bs[BK][BN];

    const int tid  = threadIdx.x;
    const int tr   = tid / (BN / TN);
    const int tc   = tid % (BN / TN);
    const int row0 = blockIdx.x * BM;
    const int col0 = blockIdx.y * BN;

    float acc[TM][TN] = {};

    for (int k0 = 0; k0 < K; k0 += BK) {
        #pragma unroll
        for (int i = tid; i < BM * (BK / 4); i += 256) {
            int m  = i / (BK / 4);
            int c4 = i % (BK / 4);
            int gm = row0 + m;
            float4 v = make_float4(0.f, 0.f, 0.f, 0.f);
            if (gm < M)
                v = *reinterpret_cast<const float4*>(A + (size_t)gm * K + k0 + c4 * 4);
            As[c4 * 4 + 0][m] = v.x;
            As[c4 * 4 + 1][m] = v.y;
            As[c4 * 4 + 2][m] = v.z;
            As[c4 * 4 + 3][m] = v.w;
        }
        {
            int i  = tid;
            int k  = i / (BN / 4);
            int c4 = i % (BN / 4);
            float4 v = *reinterpret_cast<const float4*>(B + (size_t)(k0 + k) * N + col0 + c4 * 4);
            *reinterpret_cast<float4*>(&Bs[k][c4 * 4]) = v;
        }
        __syncthreads();

        #pragma unroll
        for (int k = 0; k < BK; k++) {
            float a[TM], b[TN];
            #pragma unroll
            for (int i = 0; i < TM; i++) a[i] = As[k][tr * TM + i];
            #pragma unroll
            for (int j = 0; j < TN; j++) b[j] = Bs[k][tc * TN + j];
            #pragma unroll
            for (int i = 0; i < TM; i++)
                #pragma unroll
                for (int j = 0; j < TN; j++)
                    acc[i][j] += a[i] * b[j];
        }
        __syncthreads();
    }

    #pragma unroll
    for (int i = 0; i < TM; i++) {
        int r = row0 + tr * TM + i;
        if (r >= M) continue;
        float s = dinv[r];
        float4 o = make_float4(s * acc[i][0], s * acc[i][1], s * acc[i][2], s * acc[i][3]);
        *reinterpret_cast<float4*>(C + (size_t)r * N + col0 + tc * TN) = o;
    }
}

// ---------------------------------------------------------------------------
// aggregation: out[d] = act( dinv[d]*(sum_edges h[src]*w + h[d]) + bias )
// warp per node; lane owns VEC columns; packed int2 edge records.
// ---------------------------------------------------------------------------
template<int F, int VEC, bool RELU>
__global__ void k_agg(const float* __restrict__ h,
                      const float* __restrict__ bias,
                      float* __restrict__ out, int M) {
    static_assert(F == 32 * VEC, "lane layout");
    int warp = (blockIdx.x * blockDim.x + threadIdx.x) >> 5;
    int lane = threadIdx.x & 31;
    if (warp >= M) return;

    const int r0 = g_row[warp], r1 = g_row[warp + 1];
    const int nfull = r0 + (((r1 - r0) >> 5) << 5);
    float acc[VEC] = {};

    for (int base = r0; base < nfull; base += 32) {
        int2 rec = g_edge[base + lane];
        #pragma unroll 4
        for (int j = 0; j < 32; j++) {
            int   sj = __shfl_sync(0xffffffffu, rec.x, j);
            float wj = __int_as_float(__shfl_sync(0xffffffffu, rec.y, j));
            const float* p = h + (size_t)sj * F + lane * VEC;
            if (VEC == 4) {
                float4 v = *reinterpret_cast<const float4*>(p);
                acc[0] += v.x * wj; acc[1] += v.y * wj;
                acc[2] += v.z * wj; acc[3] += v.w * wj;
            } else {
                float2 v = *reinterpret_cast<const float2*>(p);
                acc[0] += v.x * wj; acc[1] += v.y * wj;
            }
        }
    }
    {
        int n = r1 - nfull;
        int2 rec = make_int2(0, 0);
        if (lane < n) rec = g_edge[nfull + lane];
        for (int j = 0; j < n; j++) {
            int   sj = __shfl_sync(0xffffffffu, rec.x, j);
            float wj = __int_as_float(__shfl_sync(0xffffffffu, rec.y, j));
            const float* p = h + (size_t)sj * F + lane * VEC;
            if (VEC == 4) {
                float4 v = *reinterpret_cast<const float4*>(p);
                acc[0] += v.x * wj; acc[1] += v.y * wj;
                acc[2] += v.z * wj; acc[3] += v.w * wj;
            } else {
                float2 v = *reinterpret_cast<const float2*>(p);
                acc[0] += v.x * wj; acc[1] += v.y * wj;
            }
        }
    }

    const float* ps = h + (size_t)warp * F + lane * VEC;
    float di = g_dinv[warp];
    float r[VEC];
    #pragma unroll
    for (int k = 0; k < VEC; k++) {
        float o = di * (acc[k] + ps[k]) + bias[lane * VEC + k];
        r[k] = (RELU && o < 0.0f) ? 0.0f : o;
    }
    float* po = out + (size_t)warp * F + lane * VEC;
    if (VEC == 4) *reinterpret_cast<float4*>(po) = make_float4(r[0], r[1], r[2], r[3]);
    else          *reinterpret_cast<float2*>(po) = make_float2(r[0], r[1]);
}

// ---------------------------------------------------------------------------
extern "C" void kernel_launch(void* const* d_in, const int* in_sizes, int n_in,
                              void* d_out, int out_size) {
    const float* x   = (const float*)d_in[0];
    const void*  ei  = d_in[1];
    const float* ew  = (const float*)d_in[2];
    const float* W1  = (const float*)d_in[3];
    const float* b1  = (const float*)d_in[4];
    const float* W2  = (const float*)d_in[5];
    const float* b2  = (const float*)d_in[6];
    float*       out = (float*)d_out;

    const int N1 = in_sizes[4];            // 128
    const int N2 = in_sizes[6];            // 64
    const int K1 = in_sizes[3] / N1;       // 256
    const int M  = in_sizes[0] / K1;       // 50000
    const int E  = in_sizes[2];            // 1600000
    const int NB = (M + SCAN_CHUNK - 1) / SCAN_CHUNK;

    float *p_dinv, *p_h1, *p_x2, *p_h2;
    cudaGetSymbolAddress((void**)&p_dinv, g_dinv);
    cudaGetSymbolAddress((void**)&p_h1,   g_h1);
    cudaGetSymbolAddress((void**)&p_x2,   g_x2);
    cudaGetSymbolAddress((void**)&p_h2,   g_h2);

    // --- CSR build ---
    k_detect <<<1, 256>>>((const int*)ei);
    k_zero   <<<(M + 255) / 256, 256>>>(M);
    k_histdeg<<<(E + 255) / 256, 256>>>(ei, ew, E);
    k_partial<<<NB, SCAN_CHUNK>>>(M);
    k_scanb  <<<1, 256>>>(NB);
    k_write  <<<NB, SCAN_CHUNK>>>(M);
    k_fill   <<<(E + 255) / 256, 256>>>(ei, ew, E);

    // --- layer 1 ---
    {
        dim3 grid((M + 127) / 128, N1 / 64);
        k_gemm_scale<<<grid, 256>>>(x, W1, p_dinv, p_h1, M, K1, N1);
    }
    k_agg<F1, 4, true><<<(M * 32 + 255) / 256, 256>>>(p_h1, b1, p_x2, M);

    // --- layer 2 ---
    {
        dim3 grid((M + 127) / 128, N2 / 64);
        k_gemm_scale<<<grid, 256>>>(p_x2, W2, p_dinv, p_h2, M, N1, N2);
    }
    k_agg<F2, 2, false><<<(M * 32 + 255) / 256, 256>>>(p_h2, b2, out, M);
}

// round 7
// speedup vs baseline: 3.8141x; 1.1278x over previous
#include <cuda_runtime.h>
#include <cuda_bf16.h>
#include <cstdint>

// ---------------------------------------------------------------------------
// TwoLayerGCN on GB300 — round 7: mma.sync bf16-split GEMM (base-PTX HMMA;
// tcgen05 is unavailable: harness compiles PTX for compute_103, not _103a).
//
//   deg[n]  = 1 + sum_{e: dst[e]==n} ew[e];  dinv = rsqrt(deg)
//   h       = x @ W                       (HMMA, bf16 hi/lo 3-term split)
//   out[d]  = dinv[d]*sum_e (w_e*dinv[s_e]) h[s_e] + dinv[d]^2 h[d] + b
// ---------------------------------------------------------------------------

#define MAX_NODES 50000
#define MAX_EDGES 1600000
#define F1 128
#define F2 64
#define K1DIM 256
#define SCAN_CHUNK 256
#define NUM_CHUNKS ((MAX_NODES + SCAN_CHUNK - 1) / SCAN_CHUNK)

__device__ int   g_count [MAX_NODES];
__device__ float g_deg   [MAX_NODES];
__device__ int   g_row   [MAX_NODES + 1];
__device__ int   g_cursor[MAX_NODES];
__device__ int   g_bsum  [NUM_CHUNKS];
__device__ int   g_bpre  [NUM_CHUNKS];
__device__ int2  g_edge  [MAX_EDGES];       // (src, w*dinv[src]) sorted by dst
__device__ float g_dinv  [MAX_NODES];
__device__ float g_h1    [MAX_NODES * F1];
__device__ float g_h2    [MAX_NODES * F2];
__device__ __nv_bfloat16 g_xhi [MAX_NODES * K1DIM];
__device__ __nv_bfloat16 g_xlo [MAX_NODES * K1DIM];
__device__ __nv_bfloat16 g_x2hi[MAX_NODES * F1];
__device__ __nv_bfloat16 g_x2lo[MAX_NODES * F1];
__device__ __nv_bfloat16 g_w1hi[F1 * K1DIM];   // W1^T [N=128, K=256]
__device__ __nv_bfloat16 g_w1lo[F1 * K1DIM];
__device__ __nv_bfloat16 g_w2hi[F2 * F1];      // W2^T [N=64, K=128]
__device__ __nv_bfloat16 g_w2lo[F2 * F1];
__device__ int   g_i64;

// ---------------- dtype detect / CSR build --------------------------------
__device__ __forceinline__ int load_idx(const void* ei, long long pos, int i64) {
    if (i64) return (int)((const long long*)ei)[pos];
    return ((const int*)ei)[pos];
}

__global__ void k_detect(const int* __restrict__ ei32) {
    __shared__ int nonzero;
    if (threadIdx.x == 0) nonzero = 0;
    __syncthreads();
    if (ei32[threadIdx.x * 2 + 1] != 0) atomicOr(&nonzero, 1);
    __syncthreads();
    if (threadIdx.x == 0) g_i64 = (nonzero == 0) ? 1 : 0;
}

__global__ void k_zero(int M) {
    int i = blockIdx.x * blockDim.x + threadIdx.x;
    if (i < M) { g_count[i] = 0; g_deg[i] = 1.0f; }
}

__global__ void k_histdeg(const void* __restrict__ ei,
                          const float* __restrict__ ew, int E) {
    int e = blockIdx.x * blockDim.x + threadIdx.x;
    if (e >= E) return;
    int d = load_idx(ei, (long long)E + e, g_i64);
    atomicAdd(&g_count[d], 1);
    atomicAdd(&g_deg[d], ew[e]);
}

__global__ void k_partial(int M) {
    __shared__ int wsum[8];
    int i = blockIdx.x * SCAN_CHUNK + threadIdx.x;
    int lane = threadIdx.x & 31, wid = threadIdx.x >> 5;
    int v = (i < M) ? g_count[i] : 0;
    #pragma unroll
    for (int off = 16; off > 0; off >>= 1)
        v += __shfl_xor_sync(0xffffffffu, v, off);
    if (lane == 0) wsum[wid] = v;
    __syncthreads();
    if (threadIdx.x == 0) {
        int s = 0;
        #pragma unroll
        for (int w = 0; w < 8; w++) s += wsum[w];
        g_bsum[blockIdx.x] = s;
    }
}

__global__ void k_scanb(int NB) {
    __shared__ int wpre[8];
    int tid = threadIdx.x, lane = tid & 31, wid = tid >> 5;
    int v = (tid < NB) ? g_bsum[tid] : 0;
    int inc = v;
    #pragma unroll
    for (int off = 1; off < 32; off <<= 1) {
        int t = __shfl_up_sync(0xffffffffu, inc, off);
        if (lane >= off) inc += t;
    }
    if (lane == 31) wpre[wid] = inc;
    __syncthreads();
    if (wid == 0) {
        int w = (lane < 8) ? wpre[lane] : 0;
        #pragma unroll
        for (int off = 1; off < 8; off <<= 1) {
            int t = __shfl_up_sync(0xffffffffu, w, off);
            if (lane >= off) w += t;
        }
        if (lane < 8) wpre[lane] = w;
    }
    __syncthreads();
    int excl = inc - v + (wid > 0 ? wpre[wid - 1] : 0);
    if (tid < NB) g_bpre[tid] = excl;
}

__global__ void k_write(int M) {
    __shared__ int wpre[8];
    int i = blockIdx.x * SCAN_CHUNK + threadIdx.x;
    int lane = threadIdx.x & 31, wid = threadIdx.x >> 5;
    int c = (i < M) ? g_count[i] : 0;
    int inc = c;
    #pragma unroll
    for (int off = 1; off < 32; off <<= 1) {
        int t = __shfl_up_sync(0xffffffffu, inc, off);
        if (lane >= off) inc += t;
    }
    if (lane == 31) wpre[wid] = inc;
    __syncthreads();
    if (wid == 0) {
        int w = (lane < 8) ? wpre[lane] : 0;
        #pragma unroll
        for (int off = 1; off < 8; off <<= 1) {
            int t = __shfl_up_sync(0xffffffffu, w, off);
            if (lane >= off) w += t;
        }
        if (lane < 8) wpre[lane] = w;
    }
    __syncthreads();
    int excl = inc - c + (wid > 0 ? wpre[wid - 1] : 0) + g_bpre[blockIdx.x];
    if (i < M) {
        g_row[i]    = excl;
        g_cursor[i] = excl;
        g_dinv[i]   = rsqrtf(g_deg[i]);
        if (i == M - 1) g_row[M] = excl + c;
    }
}

// fill sorted edges, folding dinv[src] into the weight
__global__ void k_fill(const void* __restrict__ ei,
                       const float* __restrict__ ew, int E) {
    int e = blockIdx.x * blockDim.x + threadIdx.x;
    if (e >= E) return;
    int i64 = g_i64;
    int s = load_idx(ei, e, i64);
    int d = load_idx(ei, (long long)E + e, i64);
    int pos = atomicAdd(&g_cursor[d], 1);
    g_edge[pos] = make_int2(s, __float_as_int(ew[e] * g_dinv[s]));
}

// ---------------- bf16 hi/lo split kernels ---------------------------------
__global__ void k_split(const float* __restrict__ x,
                        __nv_bfloat16* __restrict__ hi,
                        __nv_bfloat16* __restrict__ lo, long long n4) {
    long long i = (long long)blockIdx.x * blockDim.x + threadIdx.x;
    if (i >= n4) return;
    float4 v = *reinterpret_cast<const float4*>(x + i * 4);
    __nv_bfloat16 h0 = __float2bfloat16(v.x), h1 = __float2bfloat16(v.y);
    __nv_bfloat16 h2 = __float2bfloat16(v.z), h3 = __float2bfloat16(v.w);
    __nv_bfloat162 H0 = {h0, h1}, H1 = {h2, h3};
    __nv_bfloat162 L0 = {__float2bfloat16(v.x - __bfloat162float(h0)),
                         __float2bfloat16(v.y - __bfloat162float(h1))};
    __nv_bfloat162 L1 = {__float2bfloat16(v.z - __bfloat162float(h2)),
                         __float2bfloat16(v.w - __bfloat162float(h3))};
    *reinterpret_cast<__nv_bfloat162*>(hi + i * 4)     = H0;
    *reinterpret_cast<__nv_bfloat162*>(hi + i * 4 + 2) = H1;
    *reinterpret_cast<__nv_bfloat162*>(lo + i * 4)     = L0;
    *reinterpret_cast<__nv_bfloat162*>(lo + i * 4 + 2) = L1;
}

// W [K,N] fp32 -> W^T hi/lo [N,K] bf16
__global__ void k_prepW(const float* __restrict__ W,
                        __nv_bfloat16* __restrict__ Thi,
                        __nv_bfloat16* __restrict__ Tlo, int K, int N) {
    int i = blockIdx.x * blockDim.x + threadIdx.x;
    if (i >= K * N) return;
    int k = i / N, n = i % N;
    float v = W[i];
    __nv_bfloat16 h = __float2bfloat16(v);
    Thi[n * K + k] = h;
    Tlo[n * K + k] = __float2bfloat16(v - __bfloat162float(h));
}

// ---------------------------------------------------------------------------
// mma.sync bf16 split GEMM: C[M,N] = A @ B^T over 3 parts
//   part 0: A_hi x B_hi, part 1: A_lo x B_hi, part 2: A_hi x B_lo
// A*: [M,K] bf16 row-major; B*: [N,K] bf16 row-major (= W^T).
// Block: 256 thr = 8 warps (4 M x 2 N). BM=128, BN=N, BK=64.
// Warp tile: 32 x N/2 -> 2 m16 tiles x (N/16) n8 tiles of m16n8k16.
// ---------------------------------------------------------------------------
template<int N, int K>
__global__ void __launch_bounds__(256, 2) k_gemm_mma(
    const __nv_bfloat16* __restrict__ Ahi, const __nv_bfloat16* __restrict__ Alo,
    const __nv_bfloat16* __restrict__ Bhi, const __nv_bfloat16* __restrict__ Blo,
    float* __restrict__ C, int M)
{
    constexpr int BK = 64;
    constexpr int SP = BK + 8;        // padded stride: 36 words -> conflict-free frags
    constexpr int NT = N / 16;        // n8 subtiles per warp (8 or 4)

    __shared__ __nv_bfloat16 As[128][SP];
    __shared__ __nv_bfloat16 Bs[N][SP];

    const int tid  = threadIdx.x;
    const int wid  = tid >> 5, lane = tid & 31;
    const int wm   = wid & 3,  wn   = wid >> 2;
    const int row0 = blockIdx.x * 128;
    const int lr   = lane >> 2;       // 0..7
    const int lc   = lane & 3;        // 0..3

    float acc[2][NT][4] = {};

    for (int part = 0; part < 3; part++) {
        const __nv_bfloat16* A = (part == 1) ? Alo : Ahi;
        const __nv_bfloat16* B = (part == 2) ? Blo : Bhi;
        for (int k0 = 0; k0 < K; k0 += BK) {
            __syncthreads();
            #pragma unroll
            for (int i = tid; i < 128 * 8; i += 256) {       // A: 16B units
                int m = i >> 3, u = i & 7;
                int gm = row0 + m;
                uint4 v = make_uint4(0, 0, 0, 0);
                if (gm < M)
                    v = *reinterpret_cast<const uint4*>(A + (size_t)gm * K + k0 + u * 8);
                *reinterpret_cast<uint4*>(&As[m][u * 8]) = v;
            }
            #pragma unroll
            for (int i = tid; i < N * 8; i += 256) {         // B: 16B units
                int n = i >> 3, u = i & 7;
                uint4 v = *reinterpret_cast<const uint4*>(B + (size_t)n * K + k0 + u * 8);
                *reinterpret_cast<uint4*>(&Bs[n][u * 8]) = v;
            }
            __syncthreads();

            #pragma unroll
            for (int ks = 0; ks < BK / 16; ks++) {
                const int kw = ks * 8 + lc;                  // 32-bit word index in row
                uint32_t a[2][4];
                #pragma unroll
                for (int mt = 0; mt < 2; mt++) {
                    int r = wm * 32 + mt * 16 + lr;
                    const uint32_t* p0 = reinterpret_cast<const uint32_t*>(&As[r][0]);
                    const uint32_t* p8 = reinterpret_cast<const uint32_t*>(&As[r + 8][0]);
                    a[mt][0] = p0[kw];
                    a[mt][1] = p8[kw];
                    a[mt][2] = p0[kw + 4];
                    a[mt][3] = p8[kw + 4];
                }
                uint32_t b[NT][2];
                #pragma unroll
                for (int nt = 0; nt < NT; nt++) {
                    int n = wn * (N / 2) + nt * 8 + lr;
                    const uint32_t* pn = reinterpret_cast<const uint32_t*>(&Bs[n][0]);
                    b[nt][0] = pn[kw];
                    b[nt][1] = pn[kw + 4];
                }
                #pragma unroll
                for (int mt = 0; mt < 2; mt++)
                    #pragma unroll
                    for (int nt = 0; nt < NT; nt++) {
                        asm volatile(
                            "mma.sync.aligned.m16n8k16.row.col.f32.bf16.bf16.f32 "
                            "{%0,%1,%2,%3}, {%4,%5,%6,%7}, {%8,%9}, {%0,%1,%2,%3};"
                            : "+f"(acc[mt][nt][0]), "+f"(acc[mt][nt][1]),
                              "+f"(acc[mt][nt][2]), "+f"(acc[mt][nt][3])
                            : "r"(a[mt][0]), "r"(a[mt][1]), "r"(a[mt][2]), "r"(a[mt][3]),
                              "r"(b[nt][0]), "r"(b[nt][1]));
                    }
            }
        }
    }

    #pragma unroll
    for (int mt = 0; mt < 2; mt++) {
        int r  = row0 + wm * 32 + mt * 16 + lr;
        int r2 = r + 8;
        #pragma unroll
        for (int nt = 0; nt < NT; nt++) {
            int cb = wn * (N / 2) + nt * 8 + lc * 2;
            if (r < M)
                *reinterpret_cast<float2*>(C + (size_t)r  * N + cb) =
                    make_float2(acc[mt][nt][0], acc[mt][nt][1]);
            if (r2 < M)
                *reinterpret_cast<float2*>(C + (size_t)r2 * N + cb) =
                    make_float2(acc[mt][nt][2], acc[mt][nt][3]);
        }
    }
}

// ---------------------------------------------------------------------------
// aggregation: o[d] = act( dinv[d]*sum_e w'_e h[s] + dinv[d]^2 h[d] + bias )
// warp per node; lane owns VEC cols. SPLIT_OUT: emit bf16 hi/lo (layer1).
// ---------------------------------------------------------------------------
template<int F, int VEC, bool RELU, bool SPLIT_OUT>
__global__ void k_agg(const float* __restrict__ h,
                      const float* __restrict__ bias,
                      float* __restrict__ out_f32,
                      __nv_bfloat16* __restrict__ out_hi,
                      __nv_bfloat16* __restrict__ out_lo, int M) {
    static_assert(F == 32 * VEC, "lane layout");
    int warp = (blockIdx.x * blockDim.x + threadIdx.x) >> 5;
    int lane = threadIdx.x & 31;
    if (warp >= M) return;

    const int r0 = g_row[warp], r1 = g_row[warp + 1];
    const int nfull = r0 + (((r1 - r0) >> 5) << 5);
    float acc[VEC] = {};

    for (int base = r0; base < nfull; base += 32) {
        int2 rec = g_edge[base + lane];
        #pragma unroll 4
        for (int j = 0; j < 32; j++) {
            int   sj = __shfl_sync(0xffffffffu, rec.x, j);
            float wj = __int_as_float(__shfl_sync(0xffffffffu, rec.y, j));
            const float* p = h + (size_t)sj * F + lane * VEC;
            if (VEC == 4) {
                float4 v = *reinterpret_cast<const float4*>(p);
                acc[0] += v.x * wj; acc[1] += v.y * wj;
                acc[2] += v.z * wj; acc[3] += v.w * wj;
            } else {
                float2 v = *reinterpret_cast<const float2*>(p);
                acc[0] += v.x * wj; acc[1] += v.y * wj;
            }
        }
    }
    {
        int n = r1 - nfull;
        int2 rec = make_int2(0, 0);
        if (lane < n) rec = g_edge[nfull + lane];
        for (int j = 0; j < n; j++) {
            int   sj = __shfl_sync(0xffffffffu, rec.x, j);
            float wj = __int_as_float(__shfl_sync(0xffffffffu, rec.y, j));
            const float* p = h + (size_t)sj * F + lane * VEC;
            if (VEC == 4) {
                float4 v = *reinterpret_cast<const float4*>(p);
                acc[0] += v.x * wj; acc[1] += v.y * wj;
                acc[2] += v.z * wj; acc[3] += v.w * wj;
            } else {
                float2 v = *reinterpret_cast<const float2*>(p);
                acc[0] += v.x * wj; acc[1] += v.y * wj;
            }
        }
    }

    const float* ps = h + (size_t)warp * F + lane * VEC;
    float di  = g_dinv[warp];
    float di2 = di * di;
    float r[VEC];
    #pragma unroll
    for (int k = 0; k < VEC; k++) {
        float o = di * acc[k] + di2 * ps[k] + bias[lane * VEC + k];
        r[k] = (RELU && o < 0.0f) ? 0.0f : o;
    }
    if (SPLIT_OUT) {
        __nv_bfloat16 hi[VEC], lo[VEC];
        #pragma unroll
        for (int k = 0; k < VEC; k++) {
            hi[k] = __float2bfloat16(r[k]);
            lo[k] = __float2bfloat16(r[k] - __bfloat162float(hi[k]));
        }
        __nv_bfloat16* ph = out_hi + (size_t)warp * F + lane * VEC;
        __nv_bfloat16* pl = out_lo + (size_t)warp * F + lane * VEC;
        #pragma unroll
        for (int k = 0; k < VEC; k += 2) {
            *reinterpret_cast<__nv_bfloat162*>(ph + k) = __nv_bfloat162{hi[k], hi[k + 1]};
            *reinterpret_cast<__nv_bfloat162*>(pl + k) = __nv_bfloat162{lo[k], lo[k + 1]};
        }
    } else {
        float* po = out_f32 + (size_t)warp * F + lane * VEC;
        if (VEC == 4) *reinterpret_cast<float4*>(po) = make_float4(r[0], r[1], r[2], r[3]);
        else          *reinterpret_cast<float2*>(po) = make_float2(r[0], r[1]);
    }
}

// ---------------------------------------------------------------------------
extern "C" void kernel_launch(void* const* d_in, const int* in_sizes, int n_in,
                              void* d_out, int out_size) {
    const float* x   = (const float*)d_in[0];
    const void*  ei  = d_in[1];
    const float* ew  = (const float*)d_in[2];
    const float* W1  = (const float*)d_in[3];
    const float* b1  = (const float*)d_in[4];
    const float* W2  = (const float*)d_in[5];
    const float* b2  = (const float*)d_in[6];
    float*       out = (float*)d_out;

    const int N1 = in_sizes[4];            // 128
    const int N2 = in_sizes[6];            // 64
    const int K1 = in_sizes[3] / N1;       // 256
    const int M  = in_sizes[0] / K1;       // 50000
    const int E  = in_sizes[2];            // 1600000
    const int NB = (M + SCAN_CHUNK - 1) / SCAN_CHUNK;

    float *p_h1, *p_h2;
    __nv_bfloat16 *p_xhi, *p_xlo, *p_x2hi, *p_x2lo, *p_w1hi, *p_w1lo, *p_w2hi, *p_w2lo;
    cudaGetSymbolAddress((void**)&p_h1,   g_h1);
    cudaGetSymbolAddress((void**)&p_h2,   g_h2);
    cudaGetSymbolAddress((void**)&p_xhi,  g_xhi);
    cudaGetSymbolAddress((void**)&p_xlo,  g_xlo);
    cudaGetSymbolAddress((void**)&p_x2hi, g_x2hi);
    cudaGetSymbolAddress((void**)&p_x2lo, g_x2lo);
    cudaGetSymbolAddress((void**)&p_w1hi, g_w1hi);
    cudaGetSymbolAddress((void**)&p_w1lo, g_w1lo);
    cudaGetSymbolAddress((void**)&p_w2hi, g_w2hi);
    cudaGetSymbolAddress((void**)&p_w2lo, g_w2lo);

    // --- CSR build ---
    k_detect <<<1, 256>>>((const int*)ei);
    k_zero   <<<(M + 255) / 256, 256>>>(M);
    k_histdeg<<<(E + 255) / 256, 256>>>(ei, ew, E);
    k_partial<<<NB, SCAN_CHUNK>>>(M);
    k_scanb  <<<1, 256>>>(NB);
    k_write  <<<NB, SCAN_CHUNK>>>(M);
    k_fill   <<<(E + 255) / 256, 256>>>(ei, ew, E);

    // --- operand prep ---
    {
        long long n4 = (long long)M * K1 / 4;
        k_split<<<(unsigned)((n4 + 255) / 256), 256>>>(x, p_xhi, p_xlo, n4);
    }
    k_prepW<<<(K1 * N1 + 255) / 256, 256>>>(W1, p_w1hi, p_w1lo, K1, N1);
    k_prepW<<<(N1 * N2 + 255) / 256, 256>>>(W2, p_w2hi, p_w2lo, N1, N2);

    // --- layer 1: h1 = x @ W1 (HMMA), aggregate -> x2 (bf16 hi/lo) ---
    k_gemm_mma<128, 256><<<(M + 127) / 128, 256>>>(p_xhi, p_xlo, p_w1hi, p_w1lo, p_h1, M);
    k_agg<F1, 4, true, true><<<(M * 32 + 255) / 256, 256>>>(p_h1, b1, nullptr, p_x2hi, p_x2lo, M);

    // --- layer 2: h2 = x2 @ W2, aggregate -> out (fp32) ---
    k_gemm_mma<64, 128><<<(M + 127) / 128, 256>>>(p_x2hi, p_x2lo, p_w2hi, p_w2lo, p_h2, M);
    k_agg<F2, 2, false, false><<<(M * 32 + 255) / 256, 256>>>(p_h2, b2, out, nullptr, nullptr, M);
}

// round 8
// speedup vs baseline: 4.1743x; 1.0944x over previous
#include <cuda_runtime.h>
#include <cuda_bf16.h>
#include <cstdint>

// ---------------------------------------------------------------------------
// TwoLayerGCN on GB300 — round 8: two-stream graph fork (CSR build || GEMM prep
// + layer-1 GEMM), on top of the R7 mma.sync bf16-split pipeline.
//
//   deg[n]  = 1 + sum_{e: dst[e]==n} ew[e];  dinv = rsqrt(deg)
//   h       = x @ W                       (HMMA, bf16 hi/lo 3-term split)
//   out[d]  = dinv[d]*sum_e (w_e*dinv[s_e]) h[s_e] + dinv[d]^2 h[d] + b
// ---------------------------------------------------------------------------

#define MAX_NODES 50000
#define MAX_EDGES 1600000
#define F1 128
#define F2 64
#define K1DIM 256
#define SCAN_CHUNK 256
#define NUM_CHUNKS ((MAX_NODES + SCAN_CHUNK - 1) / SCAN_CHUNK)

__device__ int   g_count [MAX_NODES];
__device__ float g_deg   [MAX_NODES];
__device__ int   g_row   [MAX_NODES + 1];
__device__ int   g_cursor[MAX_NODES];
__device__ int   g_bsum  [NUM_CHUNKS];
__device__ int   g_bpre  [NUM_CHUNKS];
__device__ int2  g_edge  [MAX_EDGES];       // (src, w*dinv[src]) sorted by dst
__device__ float g_dinv  [MAX_NODES];
__device__ float g_h1    [MAX_NODES * F1];
__device__ float g_h2    [MAX_NODES * F2];
__device__ __nv_bfloat16 g_xhi [MAX_NODES * K1DIM];
__device__ __nv_bfloat16 g_xlo [MAX_NODES * K1DIM];
__device__ __nv_bfloat16 g_x2hi[MAX_NODES * F1];
__device__ __nv_bfloat16 g_x2lo[MAX_NODES * F1];
__device__ __nv_bfloat16 g_w1hi[F1 * K1DIM];   // W1^T [N=128, K=256]
__device__ __nv_bfloat16 g_w1lo[F1 * K1DIM];
__device__ __nv_bfloat16 g_w2hi[F2 * F1];      // W2^T [N=64, K=128]
__device__ __nv_bfloat16 g_w2lo[F2 * F1];
__device__ int   g_i64;

// ---------------- dtype detect / CSR build --------------------------------
__device__ __forceinline__ int load_idx(const void* ei, long long pos, int i64) {
    if (i64) return (int)((const long long*)ei)[pos];
    return ((const int*)ei)[pos];
}

__global__ void k_detect(const int* __restrict__ ei32) {
    __shared__ int nonzero;
    if (threadIdx.x == 0) nonzero = 0;
    __syncthreads();
    if (ei32[threadIdx.x * 2 + 1] != 0) atomicOr(&nonzero, 1);
    __syncthreads();
    if (threadIdx.x == 0) g_i64 = (nonzero == 0) ? 1 : 0;
}

__global__ void k_zero(int M) {
    int i = blockIdx.x * blockDim.x + threadIdx.x;
    if (i < M) { g_count[i] = 0; g_deg[i] = 1.0f; }
}

__global__ void k_histdeg(const void* __restrict__ ei,
                          const float* __restrict__ ew, int E) {
    int e = blockIdx.x * blockDim.x + threadIdx.x;
    if (e >= E) return;
    int d = load_idx(ei, (long long)E + e, g_i64);
    atomicAdd(&g_count[d], 1);
    atomicAdd(&g_deg[d], ew[e]);
}

__global__ void k_partial(int M) {
    __shared__ int wsum[8];
    int i = blockIdx.x * SCAN_CHUNK + threadIdx.x;
    int lane = threadIdx.x & 31, wid = threadIdx.x >> 5;
    int v = (i < M) ? g_count[i] : 0;
    #pragma unroll
    for (int off = 16; off > 0; off >>= 1)
        v += __shfl_xor_sync(0xffffffffu, v, off);
    if (lane == 0) wsum[wid] = v;
    __syncthreads();
    if (threadIdx.x == 0) {
        int s = 0;
        #pragma unroll
        for (int w = 0; w < 8; w++) s += wsum[w];
        g_bsum[blockIdx.x] = s;
    }
}

__global__ void k_scanb(int NB) {
    __shared__ int wpre[8];
    int tid = threadIdx.x, lane = tid & 31, wid = tid >> 5;
    int v = (tid < NB) ? g_bsum[tid] : 0;
    int inc = v;
    #pragma unroll
    for (int off = 1; off < 32; off <<= 1) {
        int t = __shfl_up_sync(0xffffffffu, inc, off);
        if (lane >= off) inc += t;
    }
    if (lane == 31) wpre[wid] = inc;
    __syncthreads();
    if (wid == 0) {
        int w = (lane < 8) ? wpre[lane] : 0;
        #pragma unroll
        for (int off = 1; off < 8; off <<= 1) {
            int t = __shfl_up_sync(0xffffffffu, w, off);
            if (lane >= off) w += t;
        }
        if (lane < 8) wpre[lane] = w;
    }
    __syncthreads();
    int excl = inc - v + (wid > 0 ? wpre[wid - 1] : 0);
    if (tid < NB) g_bpre[tid] = excl;
}

__global__ void k_write(int M) {
    __shared__ int wpre[8];
    int i = blockIdx.x * SCAN_CHUNK + threadIdx.x;
    int lane = threadIdx.x & 31, wid = threadIdx.x >> 5;
    int c = (i < M) ? g_count[i] : 0;
    int inc = c;
    #pragma unroll
    for (int off = 1; off < 32; off <<= 1) {
        int t = __shfl_up_sync(0xffffffffu, inc, off);
        if (lane >= off) inc += t;
    }
    if (lane == 31) wpre[wid] = inc;
    __syncthreads();
    if (wid == 0) {
        int w = (lane < 8) ? wpre[lane] : 0;
        #pragma unroll
        for (int off = 1; off < 8; off <<= 1) {
            int t = __shfl_up_sync(0xffffffffu, w, off);
            if (lane >= off) w += t;
        }
        if (lane < 8) wpre[lane] = w;
    }
    __syncthreads();
    int excl = inc - c + (wid > 0 ? wpre[wid - 1] : 0) + g_bpre[blockIdx.x];
    if (i < M) {
        g_row[i]    = excl;
        g_cursor[i] = excl;
        g_dinv[i]   = rsqrtf(g_deg[i]);
        if (i == M - 1) g_row[M] = excl + c;
    }
}

// fill sorted edges, folding dinv[src] into the weight
__global__ void k_fill(const void* __restrict__ ei,
                       const float* __restrict__ ew, int E) {
    int e = blockIdx.x * blockDim.x + threadIdx.x;
    if (e >= E) return;
    int i64 = g_i64;
    int s = load_idx(ei, e, i64);
    int d = load_idx(ei, (long long)E + e, i64);
    int pos = atomicAdd(&g_cursor[d], 1);
    g_edge[pos] = make_int2(s, __float_as_int(ew[e] * g_dinv[s]));
}

// ---------------- bf16 hi/lo split kernels ---------------------------------
__global__ void k_split(const float* __restrict__ x,
                        __nv_bfloat16* __restrict__ hi,
                        __nv_bfloat16* __restrict__ lo, long long n4) {
    long long i = (long long)blockIdx.x * blockDim.x + threadIdx.x;
    if (i >= n4) return;
    float4 v = *reinterpret_cast<const float4*>(x + i * 4);
    __nv_bfloat16 h0 = __float2bfloat16(v.x), h1 = __float2bfloat16(v.y);
    __nv_bfloat16 h2 = __float2bfloat16(v.z), h3 = __float2bfloat16(v.w);
    __nv_bfloat162 H0 = {h0, h1}, H1 = {h2, h3};
    __nv_bfloat162 L0 = {__float2bfloat16(v.x - __bfloat162float(h0)),
                         __float2bfloat16(v.y - __bfloat162float(h1))};
    __nv_bfloat162 L1 = {__float2bfloat16(v.z - __bfloat162float(h2)),
                         __float2bfloat16(v.w - __bfloat162float(h3))};
    *reinterpret_cast<__nv_bfloat162*>(hi + i * 4)     = H0;
    *reinterpret_cast<__nv_bfloat162*>(hi + i * 4 + 2) = H1;
    *reinterpret_cast<__nv_bfloat162*>(lo + i * 4)     = L0;
    *reinterpret_cast<__nv_bfloat162*>(lo + i * 4 + 2) = L1;
}

// W [K,N] fp32 -> W^T hi/lo [N,K] bf16
__global__ void k_prepW(const float* __restrict__ W,
                        __nv_bfloat16* __restrict__ Thi,
                        __nv_bfloat16* __restrict__ Tlo, int K, int N) {
    int i = blockIdx.x * blockDim.x + threadIdx.x;
    if (i >= K * N) return;
    int k = i / N, n = i % N;
    float v = W[i];
    __nv_bfloat16 h = __float2bfloat16(v);
    Thi[n * K + k] = h;
    Tlo[n * K + k] = __float2bfloat16(v - __bfloat162float(h));
}

// ---------------------------------------------------------------------------
// mma.sync bf16 split GEMM: C[M,N] = A @ B^T over 3 parts
//   part 0: A_hi x B_hi, part 1: A_lo x B_hi, part 2: A_hi x B_lo
// ---------------------------------------------------------------------------
template<int N, int K>
__global__ void __launch_bounds__(256, 2) k_gemm_mma(
    const __nv_bfloat16* __restrict__ Ahi, const __nv_bfloat16* __restrict__ Alo,
    const __nv_bfloat16* __restrict__ Bhi, const __nv_bfloat16* __restrict__ Blo,
    float* __restrict__ C, int M)
{
    constexpr int BK = 64;
    constexpr int SP = BK + 8;
    constexpr int NT = N / 16;

    __shared__ __nv_bfloat16 As[128][SP];
    __shared__ __nv_bfloat16 Bs[N][SP];

    const int tid  = threadIdx.x;
    const int wid  = tid >> 5, lane = tid & 31;
    const int wm   = wid & 3,  wn   = wid >> 2;
    const int row0 = blockIdx.x * 128;
    const int lr   = lane >> 2;
    const int lc   = lane & 3;

    float acc[2][NT][4] = {};

    for (int part = 0; part < 3; part++) {
        const __nv_bfloat16* A = (part == 1) ? Alo : Ahi;
        const __nv_bfloat16* B = (part == 2) ? Blo : Bhi;
        for (int k0 = 0; k0 < K; k0 += BK) {
            __syncthreads();
            #pragma unroll
            for (int i = tid; i < 128 * 8; i += 256) {
                int m = i >> 3, u = i & 7;
                int gm = row0 + m;
                uint4 v = make_uint4(0, 0, 0, 0);
                if (gm < M)
                    v = *reinterpret_cast<const uint4*>(A + (size_t)gm * K + k0 + u * 8);
                *reinterpret_cast<uint4*>(&As[m][u * 8]) = v;
            }
            #pragma unroll
            for (int i = tid; i < N * 8; i += 256) {
                int n = i >> 3, u = i & 7;
                uint4 v = *reinterpret_cast<const uint4*>(B + (size_t)n * K + k0 + u * 8);
                *reinterpret_cast<uint4*>(&Bs[n][u * 8]) = v;
            }
            __syncthreads();

            #pragma unroll
            for (int ks = 0; ks < BK / 16; ks++) {
                const int kw = ks * 8 + lc;
                uint32_t a[2][4];
                #pragma unroll
                for (int mt = 0; mt < 2; mt++) {
                    int r = wm * 32 + mt * 16 + lr;
                    const uint32_t* p0 = reinterpret_cast<const uint32_t*>(&As[r][0]);
                    const uint32_t* p8 = reinterpret_cast<const uint32_t*>(&As[r + 8][0]);
                    a[mt][0] = p0[kw];
                    a[mt][1] = p8[kw];
                    a[mt][2] = p0[kw + 4];
                    a[mt][3] = p8[kw + 4];
                }
                uint32_t b[NT][2];
                #pragma unroll
                for (int nt = 0; nt < NT; nt++) {
                    int n = wn * (N / 2) + nt * 8 + lr;
                    const uint32_t* pn = reinterpret_cast<const uint32_t*>(&Bs[n][0]);
                    b[nt][0] = pn[kw];
                    b[nt][1] = pn[kw + 4];
                }
                #pragma unroll
                for (int mt = 0; mt < 2; mt++)
                    #pragma unroll
                    for (int nt = 0; nt < NT; nt++) {
                        asm volatile(
                            "mma.sync.aligned.m16n8k16.row.col.f32.bf16.bf16.f32 "
                            "{%0,%1,%2,%3}, {%4,%5,%6,%7}, {%8,%9}, {%0,%1,%2,%3};"
                            : "+f"(acc[mt][nt][0]), "+f"(acc[mt][nt][1]),
                              "+f"(acc[mt][nt][2]), "+f"(acc[mt][nt][3])
                            : "r"(a[mt][0]), "r"(a[mt][1]), "r"(a[mt][2]), "r"(a[mt][3]),
                              "r"(b[nt][0]), "r"(b[nt][1]));
                    }
            }
        }
    }

    #pragma unroll
    for (int mt = 0; mt < 2; mt++) {
        int r  = row0 + wm * 32 + mt * 16 + lr;
        int r2 = r + 8;
        #pragma unroll
        for (int nt = 0; nt < NT; nt++) {
            int cb = wn * (N / 2) + nt * 8 + lc * 2;
            if (r < M)
                *reinterpret_cast<float2*>(C + (size_t)r  * N + cb) =
                    make_float2(acc[mt][nt][0], acc[mt][nt][1]);
            if (r2 < M)
                *reinterpret_cast<float2*>(C + (size_t)r2 * N + cb) =
                    make_float2(acc[mt][nt][2], acc[mt][nt][3]);
        }
    }
}

// ---------------------------------------------------------------------------
// aggregation: o[d] = act( dinv[d]*sum_e w'_e h[s] + dinv[d]^2 h[d] + bias )
// ---------------------------------------------------------------------------
template<int F, int VEC, bool RELU, bool SPLIT_OUT>
__global__ void k_agg(const float* __restrict__ h,
                      const float* __restrict__ bias,
                      float* __restrict__ out_f32,
                      __nv_bfloat16* __restrict__ out_hi,
                      __nv_bfloat16* __restrict__ out_lo, int M) {
    static_assert(F == 32 * VEC, "lane layout");
    int warp = (blockIdx.x * blockDim.x + threadIdx.x) >> 5;
    int lane = threadIdx.x & 31;
    if (warp >= M) return;

    const int r0 = g_row[warp], r1 = g_row[warp + 1];
    const int nfull = r0 + (((r1 - r0) >> 5) << 5);
    float acc[VEC] = {};

    for (int base = r0; base < nfull; base += 32) {
        int2 rec = g_edge[base + lane];
        #pragma unroll 4
        for (int j = 0; j < 32; j++) {
            int   sj = __shfl_sync(0xffffffffu, rec.x, j);
            float wj = __int_as_float(__shfl_sync(0xffffffffu, rec.y, j));
            const float* p = h + (size_t)sj * F + lane * VEC;
            if (VEC == 4) {
                float4 v = *reinterpret_cast<const float4*>(p);
                acc[0] += v.x * wj; acc[1] += v.y * wj;
                acc[2] += v.z * wj; acc[3] += v.w * wj;
            } else {
                float2 v = *reinterpret_cast<const float2*>(p);
                acc[0] += v.x * wj; acc[1] += v.y * wj;
            }
        }
    }
    {
        int n = r1 - nfull;
        int2 rec = make_int2(0, 0);
        if (lane < n) rec = g_edge[nfull + lane];
        for (int j = 0; j < n; j++) {
            int   sj = __shfl_sync(0xffffffffu, rec.x, j);
            float wj = __int_as_float(__shfl_sync(0xffffffffu, rec.y, j));
            const float* p = h + (size_t)sj * F + lane * VEC;
            if (VEC == 4) {
                float4 v = *reinterpret_cast<const float4*>(p);
                acc[0] += v.x * wj; acc[1] += v.y * wj;
                acc[2] += v.z * wj; acc[3] += v.w * wj;
            } else {
                float2 v = *reinterpret_cast<const float2*>(p);
                acc[0] += v.x * wj; acc[1] += v.y * wj;
            }
        }
    }

    const float* ps = h + (size_t)warp * F + lane * VEC;
    float di  = g_dinv[warp];
    float di2 = di * di;
    float r[VEC];
    #pragma unroll
    for (int k = 0; k < VEC; k++) {
        float o = di * acc[k] + di2 * ps[k] + bias[lane * VEC + k];
        r[k] = (RELU && o < 0.0f) ? 0.0f : o;
    }
    if (SPLIT_OUT) {
        __nv_bfloat16 hi[VEC], lo[VEC];
        #pragma unroll
        for (int k = 0; k < VEC; k++) {
            hi[k] = __float2bfloat16(r[k]);
            lo[k] = __float2bfloat16(r[k] - __bfloat162float(hi[k]));
        }
        __nv_bfloat16* ph = out_hi + (size_t)warp * F + lane * VEC;
        __nv_bfloat16* pl = out_lo + (size_t)warp * F + lane * VEC;
        #pragma unroll
        for (int k = 0; k < VEC; k += 2) {
            *reinterpret_cast<__nv_bfloat162*>(ph + k) = __nv_bfloat162{hi[k], hi[k + 1]};
            *reinterpret_cast<__nv_bfloat162*>(pl + k) = __nv_bfloat162{lo[k], lo[k + 1]};
        }
    } else {
        float* po = out_f32 + (size_t)warp * F + lane * VEC;
        if (VEC == 4) *reinterpret_cast<float4*>(po) = make_float4(r[0], r[1], r[2], r[3]);
        else          *reinterpret_cast<float2*>(po) = make_float2(r[0], r[1]);
    }
}

// ---------------------------------------------------------------------------
extern "C" void kernel_launch(void* const* d_in, const int* in_sizes, int n_in,
                              void* d_out, int out_size) {
    const float* x   = (const float*)d_in[0];
    const void*  ei  = d_in[1];
    const float* ew  = (const float*)d_in[2];
    const float* W1  = (const float*)d_in[3];
    const float* b1  = (const float*)d_in[4];
    const float* W2  = (const float*)d_in[5];
    const float* b2  = (const float*)d_in[6];
    float*       out = (float*)d_out;

    const int N1 = in_sizes[4];            // 128
    const int N2 = in_sizes[6];            // 64
    const int K1 = in_sizes[3] / N1;       // 256
    const int M  = in_sizes[0] / K1;       // 50000
    const int E  = in_sizes[2];            // 1600000
    const int NB = (M + SCAN_CHUNK - 1) / SCAN_CHUNK;

    float *p_h1, *p_h2;
    __nv_bfloat16 *p_xhi, *p_xlo, *p_x2hi, *p_x2lo, *p_w1hi, *p_w1lo, *p_w2hi, *p_w2lo;
    cudaGetSymbolAddress((void**)&p_h1,   g_h1);
    cudaGetSymbolAddress((void**)&p_h2,   g_h2);
    cudaGetSymbolAddress((void**)&p_xhi,  g_xhi);
    cudaGetSymbolAddress((void**)&p_xlo,  g_xlo);
    cudaGetSymbolAddress((void**)&p_x2hi, g_x2hi);
    cudaGetSymbolAddress((void**)&p_x2lo, g_x2lo);
    cudaGetSymbolAddress((void**)&p_w1hi, g_w1hi);
    cudaGetSymbolAddress((void**)&p_w1lo, g_w1lo);
    cudaGetSymbolAddress((void**)&p_w2hi, g_w2hi);
    cudaGetSymbolAddress((void**)&p_w2lo, g_w2lo);

    // Lazily-created side stream + fork/join events (host resources only;
    // identical device work every call). Fall back to stream 0 on failure.
    static cudaStream_t s2 = nullptr;
    static cudaEvent_t  evFork = nullptr, evJoin = nullptr;
    static bool         inited = false;
    if (!inited) {
        if (cudaStreamCreateWithFlags(&s2, cudaStreamNonBlocking) != cudaSuccess) s2 = nullptr;
        cudaEventCreateWithFlags(&evFork, cudaEventDisableTiming);
        cudaEventCreateWithFlags(&evJoin, cudaEventDisableTiming);
        inited = true;
    }
    cudaStream_t sB = s2 ? s2 : (cudaStream_t)0;
    const bool forked = (s2 != nullptr) && evFork && evJoin;

    // ---- fork ----
    if (forked) {
        cudaEventRecord(evFork, 0);
        cudaStreamWaitEvent(sB, evFork, 0);
    }

    // Stream B: GEMM-prep path (independent of CSR): split x, transpose W, gemm1
    {
        long long n4 = (long long)M * K1 / 4;
        k_split<<<(unsigned)((n4 + 255) / 256), 256, 0, sB>>>(x, p_xhi, p_xlo, n4);
    }
    k_prepW<<<(K1 * N1 + 255) / 256, 256, 0, sB>>>(W1, p_w1hi, p_w1lo, K1, N1);
    k_prepW<<<(N1 * N2 + 255) / 256, 256, 0, sB>>>(W2, p_w2hi, p_w2lo, N1, N2);
    k_gemm_mma<128, 256><<<(M + 127) / 128, 256, 0, sB>>>(p_xhi, p_xlo, p_w1hi, p_w1lo, p_h1, M);

    // Stream 0: CSR build
    k_detect <<<1, 256>>>((const int*)ei);
    k_zero   <<<(M + 255) / 256, 256>>>(M);
    k_histdeg<<<(E + 255) / 256, 256>>>(ei, ew, E);
    k_partial<<<NB, SCAN_CHUNK>>>(M);
    k_scanb  <<<1, 256>>>(NB);
    k_write  <<<NB, SCAN_CHUNK>>>(M);
    k_fill   <<<(E + 255) / 256, 256>>>(ei, ew, E);

    // ---- join ----
    if (forked) {
        cudaEventRecord(evJoin, sB);
        cudaStreamWaitEvent(0, evJoin, 0);
    }

    // layer 1 aggregate -> x2 (bf16 hi/lo)
    k_agg<F1, 4, true, true><<<(M * 32 + 255) / 256, 256>>>(p_h1, b1, nullptr, p_x2hi, p_x2lo, M);

    // layer 2: gemm + aggregate -> out
    k_gemm_mma<64, 128><<<(M + 127) / 128, 256>>>(p_x2hi, p_x2lo, p_w2hi, p_w2lo, p_h2, M);
    k_agg<F2, 2, false, false><<<(M * 32 + 255) / 256, 256>>>(p_h2, b2, out, nullptr, nullptr, M);
}